// round 7
// baseline (speedup 1.0000x reference)
#include <cuda_runtime.h>
#include <cstdio>

#define BB 2
#define HH 12
#define SS 2048
#define DH 64
#define DM 768
#define MM (BB * SS)                                   // 4096
#define ACT_ELEMS ((long long)BB * SS * DM)            // 3,145,728
#define QKV_ELEMS ((long long)BB * HH * SS * DH)       // 3,145,728
#define W_ELEMS ((long long)DM * DM)                   // 589,824
#define OUT_ELEMS ((long long)BB * SS * DM)            // 3,145,728
#define ATTN_ELEMS ((long long)BB * HH * SS * SS)      // 100,663,296

// Static device scratch (module-load allocated; no runtime allocs).
__device__ __align__(16) float g_q[3145728];
__device__ __align__(16) float g_k[3145728];
__device__ __align__(16) float g_v[3145728];
__device__ __align__(16) float g_ctx[3145728];

// Guarded global accessors (proven shell).
__device__ __forceinline__ float gld(const float* __restrict__ p, long long i, long long n) {
    return (i >= 0 && i < n) ? __ldg(p + i) : 0.f;
}
__device__ __forceinline__ void gst(float* __restrict__ p, long long i, long long n, float v) {
    if (i >= 0 && i < n) p[i] = v;
}
__device__ __forceinline__ float4 gld4(const float* __restrict__ p, long long i, long long n) {
    if (i >= 0 && i + 3 < n) return __ldg((const float4*)(p + i));
    float4 z = {0.f, 0.f, 0.f, 0.f};
    return z;
}

// 8x8 micro-tile FFMA core on k-major smem tiles (pitch PA / PB).
#define MICRO_STEP(As, PA, Ws, PB, k, off)                                      \
    {                                                                            \
        float4 a0 = *(const float4*)&(As)[(k) * (PA) + ty * 4];                  \
        float4 a1 = *(const float4*)&(As)[(k) * (PA) + (off) + ty * 4];          \
        float4 b0 = *(const float4*)&(Ws)[(k) * (PB) + tx * 4];                  \
        float4 b1 = *(const float4*)&(Ws)[(k) * (PB) + (off) + tx * 4];          \
        float a_[8] = {a0.x, a0.y, a0.z, a0.w, a1.x, a1.y, a1.z, a1.w};          \
        float b_[8] = {b0.x, b0.y, b0.z, b0.w, b1.x, b1.y, b1.z, b1.w};          \
        _Pragma("unroll")                                                        \
        for (int i = 0; i < 8; i++)                                              \
            _Pragma("unroll")                                                    \
            for (int j = 0; j < 8; j++) acc[i][j] += a_[i] * b_[j];              \
    }

// ===========================================================================
// Projection GEMM: C(head layout) = A[M,K] @ W[N,K]^T + bias.
// Tile 128x128, BK=16, 256 thr, micro 8x8 split-fragment.
// DSTSEL: 0->g_q, 1->g_k, 2->g_v.
// ===========================================================================
template <int DSTSEL>
__global__ void __launch_bounds__(256) proj_kernel(
    const float* __restrict__ A, const float* __restrict__ W,
    const float* __restrict__ bias)
{
    __shared__ float As[16 * 132];
    __shared__ float Ws[16 * 132];

    float* C = (DSTSEL == 0) ? g_q : (DSTSEL == 1) ? g_k : g_v;

    const int tid = threadIdx.x;
    const int tx = tid & 15;
    const int ty = tid >> 4;
    const int row0 = blockIdx.y * 128;
    const int col0 = blockIdx.x * 128;

    float acc[8][8];
#pragma unroll
    for (int i = 0; i < 8; i++)
#pragma unroll
        for (int j = 0; j < 8; j++) acc[i][j] = 0.f;

    for (int k0 = 0; k0 < DM; k0 += 16) {
#pragma unroll
        for (int it = 0; it < 2; it++) {
            int v = tid + it * 256;          // 0..511
            int kg = v & 3, m = v >> 2;      // kg 0..3, m 0..127
            float4 a = gld4(A, (long long)(row0 + m) * DM + k0 + kg * 4, ACT_ELEMS);
            As[(kg * 4 + 0) * 132 + m] = a.x; As[(kg * 4 + 1) * 132 + m] = a.y;
            As[(kg * 4 + 2) * 132 + m] = a.z; As[(kg * 4 + 3) * 132 + m] = a.w;
            float4 w = gld4(W, (long long)(col0 + m) * DM + k0 + kg * 4, W_ELEMS);
            Ws[(kg * 4 + 0) * 132 + m] = w.x; Ws[(kg * 4 + 1) * 132 + m] = w.y;
            Ws[(kg * 4 + 2) * 132 + m] = w.z; Ws[(kg * 4 + 3) * 132 + m] = w.w;
        }
        __syncthreads();
#pragma unroll
        for (int k = 0; k < 16; k++) MICRO_STEP(As, 132, Ws, 132, k, 64)
        __syncthreads();
    }

#pragma unroll
    for (int i = 0; i < 8; i++) {
        int gm = row0 + ((i < 4) ? (ty * 4 + i) : (64 + ty * 4 + i - 4));
        int b = gm >> 11, s = gm & 2047;
#pragma unroll
        for (int j = 0; j < 8; j++) {
            int gn = col0 + ((j < 4) ? (tx * 4 + j) : (64 + tx * 4 + j - 4));
            int h = gn >> 6, d = gn & 63;
            long long ci = (((long long)(b * HH + h)) * SS + s) * DH + d;
            gst(C, ci, QKV_ELEMS, acc[i][j] + gld(bias, gn, DM));
        }
    }
}

// ===========================================================================
// Output projection: out = gather(g_ctx) @ W_o^T + b_o.  Same tiling.
// ===========================================================================
__global__ void __launch_bounds__(256) out_proj_kernel(
    const float* __restrict__ W, const float* __restrict__ bias,
    float* __restrict__ out)
{
    __shared__ float As[16 * 132];
    __shared__ float Ws[16 * 132];

    const int tid = threadIdx.x;
    const int tx = tid & 15;
    const int ty = tid >> 4;
    const int row0 = blockIdx.y * 128;
    const int col0 = blockIdx.x * 128;

    float acc[8][8];
#pragma unroll
    for (int i = 0; i < 8; i++)
#pragma unroll
        for (int j = 0; j < 8; j++) acc[i][j] = 0.f;

    for (int k0 = 0; k0 < DM; k0 += 16) {
#pragma unroll
        for (int it = 0; it < 2; it++) {
            int v = tid + it * 256;
            int kg = v & 3, m = v >> 2;
            int gm = row0 + m;
            int gk = k0 + kg * 4;            // 4-aligned, stays inside one head
            int b = gm >> 11, s = gm & 2047;
            int h = gk >> 6, d = gk & 63;
            float4 a = gld4(g_ctx, (((long long)(b * HH + h)) * SS + s) * DH + d, QKV_ELEMS);
            As[(kg * 4 + 0) * 132 + m] = a.x; As[(kg * 4 + 1) * 132 + m] = a.y;
            As[(kg * 4 + 2) * 132 + m] = a.z; As[(kg * 4 + 3) * 132 + m] = a.w;
            float4 w = gld4(W, (long long)(col0 + m) * DM + gk, W_ELEMS);
            Ws[(kg * 4 + 0) * 132 + m] = w.x; Ws[(kg * 4 + 1) * 132 + m] = w.y;
            Ws[(kg * 4 + 2) * 132 + m] = w.z; Ws[(kg * 4 + 3) * 132 + m] = w.w;
        }
        __syncthreads();
#pragma unroll
        for (int k = 0; k < 16; k++) MICRO_STEP(As, 132, Ws, 132, k, 64)
        __syncthreads();
    }

#pragma unroll
    for (int i = 0; i < 8; i++) {
        int gm = row0 + ((i < 4) ? (ty * 4 + i) : (64 + ty * 4 + i - 4));
#pragma unroll
        for (int j = 0; j < 8; j++) {
            int gn = col0 + ((j < 4) ? (tx * 4 + j) : (64 + tx * 4 + j - 4));
            gst(out, (long long)gm * DM + gn, OUT_ELEMS, acc[i][j] + gld(bias, gn, DM));
        }
    }
}

// ===========================================================================
// Scores: attn[bh,i,j] = dot(Q[i,:], K[j,:]) / 8.
// Tile 128q x 128kcol, K=64 as 4 x BK=16. grid (S/128, S/128, B*H).
// ===========================================================================
__global__ void __launch_bounds__(256) scores_kernel(float* __restrict__ attn)
{
    __shared__ float Qs[16 * 132];
    __shared__ float Ks[16 * 132];

    const int tid = threadIdx.x;
    const int tx = tid & 15;
    const int ty = tid >> 4;
    const int bh = blockIdx.z;
    const int row0 = blockIdx.y * 128;  // q
    const int col0 = blockIdx.x * 128;  // k-col
    const long long qbase = (long long)bh * SS * DH;

    float acc[8][8];
#pragma unroll
    for (int i = 0; i < 8; i++)
#pragma unroll
        for (int j = 0; j < 8; j++) acc[i][j] = 0.f;

#pragma unroll
    for (int k0 = 0; k0 < DH; k0 += 16) {
#pragma unroll
        for (int it = 0; it < 2; it++) {
            int v = tid + it * 256;
            int kg = v & 3, m = v >> 2;
            float4 a = gld4(g_q, qbase + (long long)(row0 + m) * DH + k0 + kg * 4, QKV_ELEMS);
            Qs[(kg * 4 + 0) * 132 + m] = a.x; Qs[(kg * 4 + 1) * 132 + m] = a.y;
            Qs[(kg * 4 + 2) * 132 + m] = a.z; Qs[(kg * 4 + 3) * 132 + m] = a.w;
            float4 b = gld4(g_k, qbase + (long long)(col0 + m) * DH + k0 + kg * 4, QKV_ELEMS);
            Ks[(kg * 4 + 0) * 132 + m] = b.x; Ks[(kg * 4 + 1) * 132 + m] = b.y;
            Ks[(kg * 4 + 2) * 132 + m] = b.z; Ks[(kg * 4 + 3) * 132 + m] = b.w;
        }
        __syncthreads();
#pragma unroll
        for (int k = 0; k < 16; k++) MICRO_STEP(Qs, 132, Ks, 132, k, 64)
        __syncthreads();
    }

#pragma unroll
    for (int i = 0; i < 8; i++) {
        int gm = row0 + ((i < 4) ? (ty * 4 + i) : (64 + ty * 4 + i - 4));
        long long rbase = ((long long)bh * SS + gm) * SS + col0;
#pragma unroll
        for (int j = 0; j < 8; j++) {
            int gn = (j < 4) ? (tx * 4 + j) : (64 + tx * 4 + j - 4);
            gst(attn, rbase + gn, ATTN_ELEMS, acc[i][j] * 0.125f);
        }
    }
}

// ===========================================================================
// Row softmax over 2048 cols; one 256-thread block per row; float4 I/O.
// ===========================================================================
__global__ void __launch_bounds__(256) softmax_kernel(float* __restrict__ attn)
{
    __shared__ float red[8];
    const long long rbase = (long long)blockIdx.x * SS;
    const int tid = threadIdx.x;

    float4 v0 = gld4(attn, rbase + tid * 4, ATTN_ELEMS);
    float4 v1 = gld4(attn, rbase + 1024 + tid * 4, ATTN_ELEMS);

    float m = fmaxf(fmaxf(fmaxf(v0.x, v0.y), fmaxf(v0.z, v0.w)),
                    fmaxf(fmaxf(v1.x, v1.y), fmaxf(v1.z, v1.w)));
#pragma unroll
    for (int o = 16; o > 0; o >>= 1) m = fmaxf(m, __shfl_xor_sync(0xFFFFFFFFu, m, o));
    if ((tid & 31) == 0) red[tid >> 5] = m;
    __syncthreads();
    m = red[0];
#pragma unroll
    for (int w = 1; w < 8; w++) m = fmaxf(m, red[w]);
    __syncthreads();

    v0.x = __expf(v0.x - m); v0.y = __expf(v0.y - m);
    v0.z = __expf(v0.z - m); v0.w = __expf(v0.w - m);
    v1.x = __expf(v1.x - m); v1.y = __expf(v1.y - m);
    v1.z = __expf(v1.z - m); v1.w = __expf(v1.w - m);
    float s = v0.x + v0.y + v0.z + v0.w + v1.x + v1.y + v1.z + v1.w;
#pragma unroll
    for (int o = 16; o > 0; o >>= 1) s += __shfl_xor_sync(0xFFFFFFFFu, s, o);
    if ((tid & 31) == 0) red[tid >> 5] = s;
    __syncthreads();
    s = red[0];
#pragma unroll
    for (int w = 1; w < 8; w++) s += red[w];

    float inv = 1.f / s;
    v0.x *= inv; v0.y *= inv; v0.z *= inv; v0.w *= inv;
    v1.x *= inv; v1.y *= inv; v1.z *= inv; v1.w *= inv;

    long long i0 = rbase + tid * 4;
    long long i1 = rbase + 1024 + tid * 4;
    if (i0 + 3 < ATTN_ELEMS) *(float4*)(attn + i0) = v0;
    if (i1 + 3 < ATTN_ELEMS) *(float4*)(attn + i1) = v1;
}

// ===========================================================================
// AV: g_ctx[bh,i,d] = sum_k attn[bh,i,k] * g_v[bh,k,d].
// Tile 256q x 64d, BK=16, micro 8x8 (tx 0..7 cols, ty 0..31 rows).
// grid (S/256, B*H).
// ===========================================================================
__global__ void __launch_bounds__(256) av_kernel(const float* __restrict__ attn)
{
    __shared__ float Ps[16 * 260];   // [k][q], pitch 260
    __shared__ float Vs[16 * 68];    // [k][d], pitch 68 (direct layout)

    const int tid = threadIdx.x;
    const int tx = tid & 7;          // cols: {tx*4, 32+tx*4}
    const int ty = tid >> 3;         // rows: {ty*4, 128+ty*4}
    const int bh = blockIdx.y;
    const int row0 = blockIdx.x * 256;
    const long long pbase = (long long)bh * SS * SS;
    const long long vbase = (long long)bh * SS * DH;

    float acc[8][8];
#pragma unroll
    for (int i = 0; i < 8; i++)
#pragma unroll
        for (int j = 0; j < 8; j++) acc[i][j] = 0.f;

    for (int kk = 0; kk < SS; kk += 16) {
#pragma unroll
        for (int it = 0; it < 4; it++) {
            int v = tid + it * 256;          // 0..1023
            int kg = v & 3, m = v >> 2;      // m 0..255
            float4 a = gld4(attn, pbase + (long long)(row0 + m) * SS + kk + kg * 4, ATTN_ELEMS);
            Ps[(kg * 4 + 0) * 260 + m] = a.x; Ps[(kg * 4 + 1) * 260 + m] = a.y;
            Ps[(kg * 4 + 2) * 260 + m] = a.z; Ps[(kg * 4 + 3) * 260 + m] = a.w;
        }
        {
            int k = tid >> 4, dg = tid & 15;  // k 0..15, dg 0..15
            float4 a = gld4(g_v, vbase + (long long)(kk + k) * DH + dg * 4, QKV_ELEMS);
            *(float4*)&Vs[k * 68 + dg * 4] = a;
        }
        __syncthreads();

#pragma unroll
        for (int k = 0; k < 16; k++) {
            float4 a0 = *(const float4*)&Ps[k * 260 + ty * 4];
            float4 a1 = *(const float4*)&Ps[k * 260 + 128 + ty * 4];
            float4 b0 = *(const float4*)&Vs[k * 68 + tx * 4];
            float4 b1 = *(const float4*)&Vs[k * 68 + 32 + tx * 4];
            float a_[8] = {a0.x, a0.y, a0.z, a0.w, a1.x, a1.y, a1.z, a1.w};
            float b_[8] = {b0.x, b0.y, b0.z, b0.w, b1.x, b1.y, b1.z, b1.w};
#pragma unroll
            for (int i = 0; i < 8; i++)
#pragma unroll
                for (int j = 0; j < 8; j++) acc[i][j] += a_[i] * b_[j];
        }
        __syncthreads();
    }

#pragma unroll
    for (int i = 0; i < 8; i++) {
        int gm = row0 + ((i < 4) ? (ty * 4 + i) : (128 + ty * 4 + i - 4));
        long long obase = vbase + (long long)gm * DH;
#pragma unroll
        for (int j = 0; j < 8; j++) {
            int gd = (j < 4) ? (tx * 4 + j) : (32 + tx * 4 + j - 4);
            gst(g_ctx, obase + gd, QKV_ELEMS, acc[i][j]);
        }
    }
}

// ---------------------------------------------------------------------------
static bool s_capturing_probe()
{
    cudaStreamCaptureStatus st = cudaStreamCaptureStatusNone;
    cudaError_t e = cudaStreamIsCapturing(0, &st);
    if (e != cudaSuccess) { cudaGetLastError(); return true; }
    return st != cudaStreamCaptureStatusNone;
}

static void diag(const char* name, bool capturing)
{
    if (capturing) return;  // launches only during graph capture
    cudaError_t e = cudaDeviceSynchronize();
    fprintf(stderr, "[klaunch] %s: %s\n", name, cudaGetErrorString(e));
    cudaGetLastError();
}

extern "C" void kernel_launch(void* const* d_in, const int* in_sizes, int n_in,
                              void* d_out, int out_size)
{
    const float* query = (const float*)d_in[0];
    const float* key   = (const float*)d_in[1];
    const float* value = (const float*)d_in[2];
    const float* W_q   = (const float*)d_in[3];
    const float* b_q   = (const float*)d_in[4];
    const float* W_k   = (const float*)d_in[5];
    const float* b_k   = (const float*)d_in[6];
    const float* W_v   = (const float*)d_in[7];
    const float* b_v   = (const float*)d_in[8];
    const float* W_o   = (const float*)d_in[9];
    const float* b_o   = (const float*)d_in[10];

    float* out  = (float*)d_out;
    float* attn = out + OUT_ELEMS;  // confirmed: out_size == OUT_ELEMS + ATTN_ELEMS

    const bool capturing = s_capturing_probe();

    dim3 gProj(DM / 128, MM / 128);             // (6, 32)
    dim3 gScores(SS / 128, SS / 128, BB * HH);  // (16, 16, 24)
    dim3 gAV(SS / 256, BB * HH);                // (8, 24)

    proj_kernel<0><<<gProj, 256>>>(query, W_q, b_q);
    diag("proj_q", capturing);
    proj_kernel<1><<<gProj, 256>>>(key, W_k, b_k);
    diag("proj_k", capturing);
    proj_kernel<2><<<gProj, 256>>>(value, W_v, b_v);
    diag("proj_v", capturing);

    scores_kernel<<<gScores, 256>>>(attn);
    diag("scores", capturing);

    softmax_kernel<<<BB * HH * SS, 256>>>(attn);
    diag("softmax", capturing);

    av_kernel<<<gAV, 256>>>(attn);
    diag("av", capturing);

    out_proj_kernel<<<gProj, 256>>>(W_o, b_o, out);
    diag("out_proj", capturing);
}

// round 10
// speedup vs baseline: 1.5540x; 1.5540x over previous
#include <cuda_runtime.h>
#include <cuda_bf16.h>
#include <cstdio>

#define BB 2
#define HH 12
#define SS 2048
#define DH 64
#define DM 768
#define MM (BB * SS)                                   // 4096
#define ACT_ELEMS ((long long)BB * SS * DM)            // 3,145,728
#define QKV_ELEMS ((long long)BB * HH * SS * DH)       // 3,145,728
#define W_ELEMS ((long long)DM * DM)                   // 589,824
#define OUT_ELEMS ((long long)BB * SS * DM)            // 3,145,728
#define ATTN_ELEMS ((long long)BB * HH * SS * SS)      // 100,663,296

// Static device scratch.
__device__ __align__(16) float g_v[3145728];
__device__ __align__(16) float g_ctx[3145728];
__device__ __align__(16) __nv_bfloat16 g_qh[3145728];
__device__ __align__(16) __nv_bfloat16 g_ql[3145728];
__device__ __align__(16) __nv_bfloat16 g_kh[3145728];
__device__ __align__(16) __nv_bfloat16 g_kl[3145728];

// Guarded accessors (proven shell).
__device__ __forceinline__ float gld(const float* __restrict__ p, long long i, long long n) {
    return (i >= 0 && i < n) ? __ldg(p + i) : 0.f;
}
__device__ __forceinline__ void gst(float* __restrict__ p, long long i, long long n, float v) {
    if (i >= 0 && i < n) p[i] = v;
}
__device__ __forceinline__ float4 gld4(const float* __restrict__ p, long long i, long long n) {
    if (i >= 0 && i + 3 < n) return __ldg((const float4*)(p + i));
    float4 z = {0.f, 0.f, 0.f, 0.f};
    return z;
}
__device__ __forceinline__ void gstb(__nv_bfloat16* p, long long i, long long n, __nv_bfloat16 v) {
    if (i >= 0 && i < n) p[i] = v;
}
__device__ __forceinline__ uint2 gldb4(const __nv_bfloat16* __restrict__ p, long long i, long long n) {
    if (i >= 0 && i + 3 < n) return *(const uint2*)(p + i);
    return make_uint2(0u, 0u);
}

// bf16 hi/lo split: x ≈ hi + lo with ~16-bit effective mantissa.
__device__ __forceinline__ void f2bf2(float x, __nv_bfloat16& h, __nv_bfloat16& l) {
    h = __float2bfloat16_rn(x);
    l = __float2bfloat16_rn(x - __bfloat162float(h));
}
__device__ __forceinline__ void split4(float4 x, uint2& h, uint2& l) {
    __nv_bfloat16 h0, l0, h1, l1, h2, l2, h3, l3;
    f2bf2(x.x, h0, l0); f2bf2(x.y, h1, l1);
    f2bf2(x.z, h2, l2); f2bf2(x.w, h3, l3);
    h.x = ((unsigned)__bfloat16_as_ushort(h1) << 16) | __bfloat16_as_ushort(h0);
    h.y = ((unsigned)__bfloat16_as_ushort(h3) << 16) | __bfloat16_as_ushort(h2);
    l.x = ((unsigned)__bfloat16_as_ushort(l1) << 16) | __bfloat16_as_ushort(l0);
    l.y = ((unsigned)__bfloat16_as_ushort(l3) << 16) | __bfloat16_as_ushort(l2);
}

#define MMA_BF16(d, a, b0v, b1v)                                                 \
    asm volatile(                                                                \
        "mma.sync.aligned.m16n8k16.row.col.f32.bf16.bf16.f32 "                   \
        "{%0,%1,%2,%3}, {%4,%5,%6,%7}, {%8,%9}, {%0,%1,%2,%3};"                  \
        : "+f"((d)[0]), "+f"((d)[1]), "+f"((d)[2]), "+f"((d)[3])                 \
        : "r"((a)[0]), "r"((a)[1]), "r"((a)[2]), "r"((a)[3]), "r"(b0v), "r"(b1v));

// ===========================================================================
// Projection GEMM (round-6 config): C = A[M,K] @ W[N,K]^T + bias, head layout.
// DSTSEL 0/1 -> bf16 hi/lo (q/k); DSTSEL 2 -> fp32 g_v.
// ===========================================================================
template <int DSTSEL>
__global__ void __launch_bounds__(256) proj_kernel(
    const float* __restrict__ A, const float* __restrict__ W,
    const float* __restrict__ bias)
{
    __shared__ float As[16][132];
    __shared__ float Ws[16][68];

    const int tid = threadIdx.x;
    const int tx = tid & 15;
    const int ty = tid >> 4;
    const int row0 = blockIdx.y * 128;
    const int col0 = blockIdx.x * 64;

    float acc[8][4];
#pragma unroll
    for (int i = 0; i < 8; i++)
#pragma unroll
        for (int j = 0; j < 4; j++) acc[i][j] = 0.f;

    for (int k0 = 0; k0 < DM; k0 += 16) {
#pragma unroll
        for (int it = 0; it < 2; it++) {
            int v = tid + it * 256;
            int kg = v & 3, m = v >> 2;
            float4 a = gld4(A, (long long)(row0 + m) * DM + k0 + kg * 4, ACT_ELEMS);
            As[kg * 4 + 0][m] = a.x; As[kg * 4 + 1][m] = a.y;
            As[kg * 4 + 2][m] = a.z; As[kg * 4 + 3][m] = a.w;
        }
        {
            int kg = tid & 3, n = tid >> 2;
            float4 w = gld4(W, (long long)(col0 + n) * DM + k0 + kg * 4, W_ELEMS);
            Ws[kg * 4 + 0][n] = w.x; Ws[kg * 4 + 1][n] = w.y;
            Ws[kg * 4 + 2][n] = w.z; Ws[kg * 4 + 3][n] = w.w;
        }
        __syncthreads();

#pragma unroll
        for (int k = 0; k < 16; k++) {
            float4 a0 = *(const float4*)&As[k][ty * 8];
            float4 a1 = *(const float4*)&As[k][ty * 8 + 4];
            float4 bb = *(const float4*)&Ws[k][tx * 4];
            float a_[8] = {a0.x, a0.y, a0.z, a0.w, a1.x, a1.y, a1.z, a1.w};
            float b_[4] = {bb.x, bb.y, bb.z, bb.w};
#pragma unroll
            for (int i = 0; i < 8; i++)
#pragma unroll
                for (int j = 0; j < 4; j++) acc[i][j] += a_[i] * b_[j];
        }
        __syncthreads();
    }

#pragma unroll
    for (int i = 0; i < 8; i++) {
        int gm = row0 + ty * 8 + i;
        int b = gm >> 11, s = gm & 2047;
#pragma unroll
        for (int j = 0; j < 4; j++) {
            int gn = col0 + tx * 4 + j;
            int h = gn >> 6, d = gn & 63;
            long long ci = (((long long)(b * HH + h)) * SS + s) * DH + d;
            float val = acc[i][j] + gld(bias, gn, DM);
            if (DSTSEL == 2) {
                gst(g_v, ci, QKV_ELEMS, val);
            } else {
                __nv_bfloat16 hh, ll;
                f2bf2(val, hh, ll);
                gstb((DSTSEL == 0) ? g_qh : g_kh, ci, QKV_ELEMS, hh);
                gstb((DSTSEL == 0) ? g_ql : g_kl, ci, QKV_ELEMS, ll);
            }
        }
    }
}

// ===========================================================================
// Output projection (round-6 config): out = gather(g_ctx) @ W_o^T + b_o.
// ===========================================================================
__global__ void __launch_bounds__(256) out_proj_kernel(
    const float* __restrict__ W, const float* __restrict__ bias,
    float* __restrict__ out)
{
    __shared__ float As[16][132];
    __shared__ float Ws[16][68];

    const int tid = threadIdx.x;
    const int tx = tid & 15;
    const int ty = tid >> 4;
    const int row0 = blockIdx.y * 128;
    const int col0 = blockIdx.x * 64;

    float acc[8][4];
#pragma unroll
    for (int i = 0; i < 8; i++)
#pragma unroll
        for (int j = 0; j < 4; j++) acc[i][j] = 0.f;

    for (int k0 = 0; k0 < DM; k0 += 16) {
#pragma unroll
        for (int it = 0; it < 2; it++) {
            int v = tid + it * 256;
            int kg = v & 3, m = v >> 2;
            int gm = row0 + m;
            int gk = k0 + kg * 4;
            int b = gm >> 11, s = gm & 2047;
            int h = gk >> 6, d = gk & 63;
            float4 a = gld4(g_ctx, (((long long)(b * HH + h)) * SS + s) * DH + d, QKV_ELEMS);
            As[kg * 4 + 0][m] = a.x; As[kg * 4 + 1][m] = a.y;
            As[kg * 4 + 2][m] = a.z; As[kg * 4 + 3][m] = a.w;
        }
        {
            int kg = tid & 3, n = tid >> 2;
            float4 w = gld4(W, (long long)(col0 + n) * DM + k0 + kg * 4, W_ELEMS);
            Ws[kg * 4 + 0][n] = w.x; Ws[kg * 4 + 1][n] = w.y;
            Ws[kg * 4 + 2][n] = w.z; Ws[kg * 4 + 3][n] = w.w;
        }
        __syncthreads();

#pragma unroll
        for (int k = 0; k < 16; k++) {
            float4 a0 = *(const float4*)&As[k][ty * 8];
            float4 a1 = *(const float4*)&As[k][ty * 8 + 4];
            float4 bb = *(const float4*)&Ws[k][tx * 4];
            float a_[8] = {a0.x, a0.y, a0.z, a0.w, a1.x, a1.y, a1.z, a1.w};
            float b_[4] = {bb.x, bb.y, bb.z, bb.w};
#pragma unroll
            for (int i = 0; i < 8; i++)
#pragma unroll
                for (int j = 0; j < 4; j++) acc[i][j] += a_[i] * b_[j];
        }
        __syncthreads();
    }

#pragma unroll
    for (int i = 0; i < 8; i++) {
        int gm = row0 + ty * 8 + i;
#pragma unroll
        for (int j = 0; j < 4; j++) {
            int gn = col0 + tx * 4 + j;
            gst(out, (long long)gm * DM + gn, OUT_ELEMS, acc[i][j] + gld(bias, gn, DM));
        }
    }
}

// ===========================================================================
// Scores via bf16x3 mma: attn[bh,i,j] = q_i·k_j / 8.
// Block 128q x 128k, 8 warps (warp tile 32x64), DH=64 resident.
// Dyn smem: Qh|Ql|Kh|Kl, each [128][72] bf16 = 18432 B -> 73728 B.
// ===========================================================================
#define SCORES_SMEM 73728

__global__ void __launch_bounds__(256) scores_mma_kernel(float* __restrict__ attn)
{
    extern __shared__ __align__(16) char smraw[];
    __nv_bfloat16* Qh_s = (__nv_bfloat16*)smraw;
    __nv_bfloat16* Ql_s = (__nv_bfloat16*)(smraw + 18432);
    __nv_bfloat16* Kh_s = (__nv_bfloat16*)(smraw + 36864);
    __nv_bfloat16* Kl_s = (__nv_bfloat16*)(smraw + 55296);

    const int tid = threadIdx.x;
    const int warp = tid >> 5;
    const int lane = tid & 31;
    const int warp_m = warp & 3;      // 4 warps over 128 rows (32 each)
    const int warp_n = warp >> 2;     // 2 warps over 128 cols (64 each)
    const int bh = blockIdx.z;
    const int row0 = blockIdx.y * 128;
    const int col0 = blockIdx.x * 128;
    const long long hb = (long long)bh * SS * DH;

    // Fill smem (uint2 = 4 bf16 per op). 8 x 256 = 2048 quads = full tiles.
#pragma unroll
    for (int it = 0; it < 8; it++) {
        int v = tid + it * 256;
        int m = v >> 4;              // 0..127
        int kq = (v & 15) * 4;       // 0..60
        long long qi = hb + (long long)(row0 + m) * DH + kq;
        *(uint2*)&Qh_s[m * 72 + kq] = gldb4(g_qh, qi, QKV_ELEMS);
        *(uint2*)&Ql_s[m * 72 + kq] = gldb4(g_ql, qi, QKV_ELEMS);
        long long ki = hb + (long long)(col0 + m) * DH + kq;
        *(uint2*)&Kh_s[m * 72 + kq] = gldb4(g_kh, ki, QKV_ELEMS);
        *(uint2*)&Kl_s[m * 72 + kq] = gldb4(g_kl, ki, QKV_ELEMS);
    }
    __syncthreads();

    const int lr = lane >> 2;
    const int lc2 = (lane & 3) * 2;

    float acc[2][8][4];
#pragma unroll
    for (int a = 0; a < 2; a++)
#pragma unroll
        for (int b = 0; b < 8; b++)
#pragma unroll
            for (int c = 0; c < 4; c++) acc[a][b][c] = 0.f;

#pragma unroll
    for (int kc = 0; kc < 4; kc++) {
        int k0 = kc * 16;
        unsigned ah[2][4], al[2][4];
#pragma unroll
        for (int mt = 0; mt < 2; mt++) {
            int r = warp_m * 32 + mt * 16 + lr;
            ah[mt][0] = *(unsigned*)&Qh_s[r * 72 + k0 + lc2];
            ah[mt][1] = *(unsigned*)&Qh_s[(r + 8) * 72 + k0 + lc2];
            ah[mt][2] = *(unsigned*)&Qh_s[r * 72 + k0 + 8 + lc2];
            ah[mt][3] = *(unsigned*)&Qh_s[(r + 8) * 72 + k0 + 8 + lc2];
            al[mt][0] = *(unsigned*)&Ql_s[r * 72 + k0 + lc2];
            al[mt][1] = *(unsigned*)&Ql_s[(r + 8) * 72 + k0 + lc2];
            al[mt][2] = *(unsigned*)&Ql_s[r * 72 + k0 + 8 + lc2];
            al[mt][3] = *(unsigned*)&Ql_s[(r + 8) * 72 + k0 + 8 + lc2];
        }
#pragma unroll
        for (int nt = 0; nt < 8; nt++) {
            int c = warp_n * 64 + nt * 8 + lr;
            unsigned bh0 = *(unsigned*)&Kh_s[c * 72 + k0 + lc2];
            unsigned bh1 = *(unsigned*)&Kh_s[c * 72 + k0 + 8 + lc2];
            unsigned bl0 = *(unsigned*)&Kl_s[c * 72 + k0 + lc2];
            unsigned bl1 = *(unsigned*)&Kl_s[c * 72 + k0 + 8 + lc2];
#pragma unroll
            for (int mt = 0; mt < 2; mt++) {
                MMA_BF16(acc[mt][nt], ah[mt], bh0, bh1);
                MMA_BF16(acc[mt][nt], ah[mt], bl0, bl1);
                MMA_BF16(acc[mt][nt], al[mt], bh0, bh1);
            }
        }
    }

#pragma unroll
    for (int mt = 0; mt < 2; mt++) {
        int mrow = row0 + warp_m * 32 + mt * 16 + lr;
#pragma unroll
        for (int nt = 0; nt < 8; nt++) {
            int ncol = col0 + warp_n * 64 + nt * 8 + lc2;
            long long i0 = ((long long)bh * SS + mrow) * SS + ncol;
            long long i2 = ((long long)bh * SS + mrow + 8) * SS + ncol;
            gst(attn, i0,     ATTN_ELEMS, acc[mt][nt][0] * 0.125f);
            gst(attn, i0 + 1, ATTN_ELEMS, acc[mt][nt][1] * 0.125f);
            gst(attn, i2,     ATTN_ELEMS, acc[mt][nt][2] * 0.125f);
            gst(attn, i2 + 1, ATTN_ELEMS, acc[mt][nt][3] * 0.125f);
        }
    }
}

// ===========================================================================
// Row softmax over 2048 cols (round-6, unchanged).
// ===========================================================================
__global__ void __launch_bounds__(256) softmax_kernel(float* __restrict__ attn)
{
    __shared__ float red[8];
    const long long rbase = (long long)blockIdx.x * SS;
    const int tid = threadIdx.x;

    float4 v0 = gld4(attn, rbase + tid * 4, ATTN_ELEMS);
    float4 v1 = gld4(attn, rbase + 1024 + tid * 4, ATTN_ELEMS);

    float m = fmaxf(fmaxf(fmaxf(v0.x, v0.y), fmaxf(v0.z, v0.w)),
                    fmaxf(fmaxf(v1.x, v1.y), fmaxf(v1.z, v1.w)));
#pragma unroll
    for (int o = 16; o > 0; o >>= 1) m = fmaxf(m, __shfl_xor_sync(0xFFFFFFFFu, m, o));
    if ((tid & 31) == 0) red[tid >> 5] = m;
    __syncthreads();
    m = red[0];
#pragma unroll
    for (int w = 1; w < 8; w++) m = fmaxf(m, red[w]);
    __syncthreads();

    v0.x = __expf(v0.x - m); v0.y = __expf(v0.y - m);
    v0.z = __expf(v0.z - m); v0.w = __expf(v0.w - m);
    v1.x = __expf(v1.x - m); v1.y = __expf(v1.y - m);
    v1.z = __expf(v1.z - m); v1.w = __expf(v1.w - m);
    float s = v0.x + v0.y + v0.z + v0.w + v1.x + v1.y + v1.z + v1.w;
#pragma unroll
    for (int o = 16; o > 0; o >>= 1) s += __shfl_xor_sync(0xFFFFFFFFu, s, o);
    if ((tid & 31) == 0) red[tid >> 5] = s;
    __syncthreads();
    s = red[0];
#pragma unroll
    for (int w = 1; w < 8; w++) s += red[w];

    float inv = 1.f / s;
    v0.x *= inv; v0.y *= inv; v0.z *= inv; v0.w *= inv;
    v1.x *= inv; v1.y *= inv; v1.z *= inv; v1.w *= inv;

    long long i0 = rbase + tid * 4;
    long long i1 = rbase + 1024 + tid * 4;
    if (i0 + 3 < ATTN_ELEMS) *(float4*)(attn + i0) = v0;
    if (i1 + 3 < ATTN_ELEMS) *(float4*)(attn + i1) = v1;
}

// ===========================================================================
// AV via bf16x3 mma: ctx[bh,i,d] = sum_k attn[bh,i,k] * v[bh,k,d].
// Block 128q x 64d, 8 warps (warp tile 32x32), BK=64, in-kernel conversion.
// Dyn smem: Ph|Pl [128][72] + Vth|Vtl [64][72] bf16 -> 55296 B.
// ===========================================================================
#define AV_SMEM 55296

__global__ void __launch_bounds__(256) av_mma_kernel(const float* __restrict__ attn)
{
    extern __shared__ __align__(16) char smraw[];
    __nv_bfloat16* Ph_s  = (__nv_bfloat16*)smraw;
    __nv_bfloat16* Pl_s  = (__nv_bfloat16*)(smraw + 18432);
    __nv_bfloat16* Vth_s = (__nv_bfloat16*)(smraw + 36864);
    __nv_bfloat16* Vtl_s = (__nv_bfloat16*)(smraw + 46080);

    const int tid = threadIdx.x;
    const int warp = tid >> 5;
    const int lane = tid & 31;
    const int warp_m = warp & 3;      // 4 warps x 32 rows
    const int warp_n = warp >> 2;     // 2 warps x 32 cols
    const int bh = blockIdx.y;
    const int row0 = blockIdx.x * 128;
    const long long pbase = (long long)bh * SS * SS;
    const long long vbase = (long long)bh * SS * DH;

    const int lr = lane >> 2;
    const int lc2 = (lane & 3) * 2;

    float acc[2][4][4];
#pragma unroll
    for (int a = 0; a < 2; a++)
#pragma unroll
        for (int b = 0; b < 4; b++)
#pragma unroll
            for (int c = 0; c < 4; c++) acc[a][b][c] = 0.f;

    for (int kk = 0; kk < SS; kk += 64) {
        // P tile 128x64 fp32 -> hi/lo bf16 (8 x 256 = 2048 quads = full tile)
#pragma unroll
        for (int it = 0; it < 8; it++) {
            int v = tid + it * 256;
            int m = v >> 4;
            int kq = (v & 15) * 4;
            float4 p = gld4(attn, pbase + (long long)(row0 + m) * SS + kk + kq, ATTN_ELEMS);
            uint2 h, l;
            split4(p, h, l);
            *(uint2*)&Ph_s[m * 72 + kq] = h;
            *(uint2*)&Pl_s[m * 72 + kq] = l;
        }
        // V tile 64x64 fp32 -> transposed hi/lo bf16 [d][k]
        // FIX (round-9 NaN): 4 x 256 threads covers all 64 k-rows (was 1 pass = 16 rows).
#pragma unroll
        for (int it = 0; it < 4; it++) {
            int v = tid + it * 256;          // 0..1023
            int k = v >> 4;                  // 0..63
            int dq = (v & 15) * 4;           // 0..60
            float4 vv = gld4(g_v, vbase + (long long)(kk + k) * DH + dq, QKV_ELEMS);
            __nv_bfloat16 h, l;
            f2bf2(vv.x, h, l); Vth_s[(dq + 0) * 72 + k] = h; Vtl_s[(dq + 0) * 72 + k] = l;
            f2bf2(vv.y, h, l); Vth_s[(dq + 1) * 72 + k] = h; Vtl_s[(dq + 1) * 72 + k] = l;
            f2bf2(vv.z, h, l); Vth_s[(dq + 2) * 72 + k] = h; Vtl_s[(dq + 2) * 72 + k] = l;
            f2bf2(vv.w, h, l); Vth_s[(dq + 3) * 72 + k] = h; Vtl_s[(dq + 3) * 72 + k] = l;
        }
        __syncthreads();

#pragma unroll
        for (int kc = 0; kc < 4; kc++) {
            int k0 = kc * 16;
            unsigned ah[2][4], al[2][4];
#pragma unroll
            for (int mt = 0; mt < 2; mt++) {
                int r = warp_m * 32 + mt * 16 + lr;
                ah[mt][0] = *(unsigned*)&Ph_s[r * 72 + k0 + lc2];
                ah[mt][1] = *(unsigned*)&Ph_s[(r + 8) * 72 + k0 + lc2];
                ah[mt][2] = *(unsigned*)&Ph_s[r * 72 + k0 + 8 + lc2];
                ah[mt][3] = *(unsigned*)&Ph_s[(r + 8) * 72 + k0 + 8 + lc2];
                al[mt][0] = *(unsigned*)&Pl_s[r * 72 + k0 + lc2];
                al[mt][1] = *(unsigned*)&Pl_s[(r + 8) * 72 + k0 + lc2];
                al[mt][2] = *(unsigned*)&Pl_s[r * 72 + k0 + 8 + lc2];
                al[mt][3] = *(unsigned*)&Pl_s[(r + 8) * 72 + k0 + 8 + lc2];
            }
#pragma unroll
            for (int nt = 0; nt < 4; nt++) {
                int c = warp_n * 32 + nt * 8 + lr;
                unsigned bh0 = *(unsigned*)&Vth_s[c * 72 + k0 + lc2];
                unsigned bh1 = *(unsigned*)&Vth_s[c * 72 + k0 + 8 + lc2];
                unsigned bl0 = *(unsigned*)&Vtl_s[c * 72 + k0 + lc2];
                unsigned bl1 = *(unsigned*)&Vtl_s[c * 72 + k0 + 8 + lc2];
#pragma unroll
                for (int mt = 0; mt < 2; mt++) {
                    MMA_BF16(acc[mt][nt], ah[mt], bh0, bh1);
                    MMA_BF16(acc[mt][nt], ah[mt], bl0, bl1);
                    MMA_BF16(acc[mt][nt], al[mt], bh0, bh1);
                }
            }
        }
        __syncthreads();
    }

#pragma unroll
    for (int mt = 0; mt < 2; mt++) {
        int mrow = row0 + warp_m * 32 + mt * 16 + lr;
#pragma unroll
        for (int nt = 0; nt < 4; nt++) {
            int dcol = warp_n * 32 + nt * 8 + lc2;
            long long i0 = vbase + (long long)mrow * DH + dcol;
            long long i2 = vbase + (long long)(mrow + 8) * DH + dcol;
            gst(g_ctx, i0,     QKV_ELEMS, acc[mt][nt][0]);
            gst(g_ctx, i0 + 1, QKV_ELEMS, acc[mt][nt][1]);
            gst(g_ctx, i2,     QKV_ELEMS, acc[mt][nt][2]);
            gst(g_ctx, i2 + 1, QKV_ELEMS, acc[mt][nt][3]);
        }
    }
}

// ---------------------------------------------------------------------------
static bool s_capturing_probe()
{
    cudaStreamCaptureStatus st = cudaStreamCaptureStatusNone;
    cudaError_t e = cudaStreamIsCapturing(0, &st);
    if (e != cudaSuccess) { cudaGetLastError(); return true; }
    return st != cudaStreamCaptureStatusNone;
}

static void diag(const char* name, bool capturing)
{
    if (capturing) return;  // launches only during graph capture
    cudaError_t e = cudaDeviceSynchronize();
    fprintf(stderr, "[klaunch] %s: %s\n", name, cudaGetErrorString(e));
    cudaGetLastError();
}

extern "C" void kernel_launch(void* const* d_in, const int* in_sizes, int n_in,
                              void* d_out, int out_size)
{
    const float* query = (const float*)d_in[0];
    const float* key   = (const float*)d_in[1];
    const float* value = (const float*)d_in[2];
    const float* W_q   = (const float*)d_in[3];
    const float* b_q   = (const float*)d_in[4];
    const float* W_k   = (const float*)d_in[5];
    const float* b_k   = (const float*)d_in[6];
    const float* W_v   = (const float*)d_in[7];
    const float* b_v   = (const float*)d_in[8];
    const float* W_o   = (const float*)d_in[9];
    const float* b_o   = (const float*)d_in[10];

    float* out  = (float*)d_out;
    float* attn = out + OUT_ELEMS;  // confirmed: out_size == OUT_ELEMS + ATTN_ELEMS

    const bool capturing = s_capturing_probe();

    cudaFuncSetAttribute(scores_mma_kernel,
                         cudaFuncAttributeMaxDynamicSharedMemorySize, SCORES_SMEM);
    cudaFuncSetAttribute(av_mma_kernel,
                         cudaFuncAttributeMaxDynamicSharedMemorySize, AV_SMEM);

    dim3 gProj(DM / 64, MM / 128);              // (12, 32)
    dim3 gScores(SS / 128, SS / 128, BB * HH);  // (16, 16, 24)
    dim3 gAV(SS / 128, BB * HH);                // (16, 24)

    proj_kernel<0><<<gProj, 256>>>(query, W_q, b_q);
    diag("proj_q", capturing);
    proj_kernel<1><<<gProj, 256>>>(key, W_k, b_k);
    diag("proj_k", capturing);
    proj_kernel<2><<<gProj, 256>>>(value, W_v, b_v);
    diag("proj_v", capturing);

    scores_mma_kernel<<<gScores, 256, SCORES_SMEM>>>(attn);
    diag("scores_mma", capturing);

    softmax_kernel<<<BB * HH * SS, 256>>>(attn);
    diag("softmax", capturing);

    av_mma_kernel<<<gAV, 256, AV_SMEM>>>(attn);
    diag("av_mma", capturing);

    out_proj_kernel<<<gProj, 256>>>(W_o, b_o, out);
    diag("out_proj", capturing);
}

// round 11
// speedup vs baseline: 1.7002x; 1.0940x over previous
#include <cuda_runtime.h>
#include <cuda_bf16.h>
#include <cstdio>

#define BB 2
#define HH 12
#define SS 2048
#define DH 64
#define DM 768
#define MM (BB * SS)                                   // 4096
#define ACT_ELEMS ((long long)BB * SS * DM)            // 3,145,728
#define QKV_ELEMS ((long long)BB * HH * SS * DH)       // 3,145,728
#define W_ELEMS ((long long)DM * DM)                   // 589,824
#define OUT_ELEMS ((long long)BB * SS * DM)            // 3,145,728
#define ATTN_ELEMS ((long long)BB * HH * SS * SS)      // 100,663,296

// Static device scratch.
__device__ __align__(16) float g_v[3145728];
__device__ __align__(16) __nv_bfloat16 g_qh[3145728];
__device__ __align__(16) __nv_bfloat16 g_ql[3145728];
__device__ __align__(16) __nv_bfloat16 g_kh[3145728];
__device__ __align__(16) __nv_bfloat16 g_kl[3145728];
__device__ __align__(16) __nv_bfloat16 g_ctxh[3145728];
__device__ __align__(16) __nv_bfloat16 g_ctxl[3145728];

// Guarded accessors (proven shell).
__device__ __forceinline__ float gld(const float* __restrict__ p, long long i, long long n) {
    return (i >= 0 && i < n) ? __ldg(p + i) : 0.f;
}
__device__ __forceinline__ void gst(float* __restrict__ p, long long i, long long n, float v) {
    if (i >= 0 && i < n) p[i] = v;
}
__device__ __forceinline__ float4 gld4(const float* __restrict__ p, long long i, long long n) {
    if (i >= 0 && i + 3 < n) return __ldg((const float4*)(p + i));
    float4 z = {0.f, 0.f, 0.f, 0.f};
    return z;
}
__device__ __forceinline__ void gstb(__nv_bfloat16* p, long long i, long long n, __nv_bfloat16 v) {
    if (i >= 0 && i < n) p[i] = v;
}
__device__ __forceinline__ uint2 gldb4(const __nv_bfloat16* __restrict__ p, long long i, long long n) {
    if (i >= 0 && i + 3 < n) return *(const uint2*)(p + i);
    return make_uint2(0u, 0u);
}

// bf16 hi/lo split: x ≈ hi + lo with ~16-bit effective mantissa.
__device__ __forceinline__ void f2bf2(float x, __nv_bfloat16& h, __nv_bfloat16& l) {
    h = __float2bfloat16_rn(x);
    l = __float2bfloat16_rn(x - __bfloat162float(h));
}
__device__ __forceinline__ void split4(float4 x, uint2& h, uint2& l) {
    __nv_bfloat16 h0, l0, h1, l1, h2, l2, h3, l3;
    f2bf2(x.x, h0, l0); f2bf2(x.y, h1, l1);
    f2bf2(x.z, h2, l2); f2bf2(x.w, h3, l3);
    h.x = ((unsigned)__bfloat16_as_ushort(h1) << 16) | __bfloat16_as_ushort(h0);
    h.y = ((unsigned)__bfloat16_as_ushort(h3) << 16) | __bfloat16_as_ushort(h2);
    l.x = ((unsigned)__bfloat16_as_ushort(l1) << 16) | __bfloat16_as_ushort(l0);
    l.y = ((unsigned)__bfloat16_as_ushort(l3) << 16) | __bfloat16_as_ushort(l2);
}

#define MMA_BF16(d, a, b0v, b1v)                                                 \
    asm volatile(                                                                \
        "mma.sync.aligned.m16n8k16.row.col.f32.bf16.bf16.f32 "                   \
        "{%0,%1,%2,%3}, {%4,%5,%6,%7}, {%8,%9}, {%0,%1,%2,%3};"                  \
        : "+f"((d)[0]), "+f"((d)[1]), "+f"((d)[2]), "+f"((d)[3])                 \
        : "r"((a)[0]), "r"((a)[1]), "r"((a)[2]), "r"((a)[3]), "r"(b0v), "r"(b1v));

// Shared mma-GEMM geometry: block 128m x 64n, 8 warps (warp tile 32x32), BK=32.
// smem rows pitch 40 bf16 (80B) -> conflict-free fragment LDS.

// ===========================================================================
// Projection GEMM via bf16x3 mma: C = A[M,K] @ W[N,K]^T + bias, head layout.
// DSTSEL 0 -> g_qh/g_ql, 1 -> g_kh/g_kl, 2 -> g_v (fp32).
// ===========================================================================
template <int DSTSEL>
__global__ void __launch_bounds__(256) proj_mma_kernel(
    const float* __restrict__ A, const float* __restrict__ W,
    const float* __restrict__ bias)
{
    __shared__ __nv_bfloat16 Ah_s[128 * 40];
    __shared__ __nv_bfloat16 Al_s[128 * 40];
    __shared__ __nv_bfloat16 Wh_s[64 * 40];
    __shared__ __nv_bfloat16 Wl_s[64 * 40];

    const int tid = threadIdx.x;
    const int warp = tid >> 5, lane = tid & 31;
    const int warp_m = warp & 3, warp_n = warp >> 2;
    const int row0 = blockIdx.y * 128, col0 = blockIdx.x * 64;
    const int lr = lane >> 2, lc2 = (lane & 3) * 2;

    float acc[2][4][4];
#pragma unroll
    for (int a = 0; a < 2; a++)
#pragma unroll
        for (int b = 0; b < 4; b++)
#pragma unroll
            for (int c = 0; c < 4; c++) acc[a][b][c] = 0.f;

    for (int k0 = 0; k0 < DM; k0 += 32) {
        // A tile 128x32 fp32 -> hi/lo (4 x 256 = 1024 quads = full tile)
#pragma unroll
        for (int it = 0; it < 4; it++) {
            int v = tid + it * 256;
            int m = v >> 3;              // 0..127
            int kq = (v & 7) * 4;        // 0..28
            float4 a = gld4(A, (long long)(row0 + m) * DM + k0 + kq, ACT_ELEMS);
            uint2 h, l;
            split4(a, h, l);
            *(uint2*)&Ah_s[m * 40 + kq] = h;
            *(uint2*)&Al_s[m * 40 + kq] = l;
        }
        // W tile 64x32 fp32 -> hi/lo (2 x 256 = 512 quads = full tile)
#pragma unroll
        for (int it = 0; it < 2; it++) {
            int v = tid + it * 256;
            int n = v >> 3;              // 0..63
            int kq = (v & 7) * 4;
            float4 w = gld4(W, (long long)(col0 + n) * DM + k0 + kq, W_ELEMS);
            uint2 h, l;
            split4(w, h, l);
            *(uint2*)&Wh_s[n * 40 + kq] = h;
            *(uint2*)&Wl_s[n * 40 + kq] = l;
        }
        __syncthreads();

#pragma unroll
        for (int kc = 0; kc < 32; kc += 16) {
            unsigned ah[2][4], al[2][4];
#pragma unroll
            for (int mt = 0; mt < 2; mt++) {
                int r = warp_m * 32 + mt * 16 + lr;
                ah[mt][0] = *(unsigned*)&Ah_s[r * 40 + kc + lc2];
                ah[mt][1] = *(unsigned*)&Ah_s[(r + 8) * 40 + kc + lc2];
                ah[mt][2] = *(unsigned*)&Ah_s[r * 40 + kc + 8 + lc2];
                ah[mt][3] = *(unsigned*)&Ah_s[(r + 8) * 40 + kc + 8 + lc2];
                al[mt][0] = *(unsigned*)&Al_s[r * 40 + kc + lc2];
                al[mt][1] = *(unsigned*)&Al_s[(r + 8) * 40 + kc + lc2];
                al[mt][2] = *(unsigned*)&Al_s[r * 40 + kc + 8 + lc2];
                al[mt][3] = *(unsigned*)&Al_s[(r + 8) * 40 + kc + 8 + lc2];
            }
#pragma unroll
            for (int nt = 0; nt < 4; nt++) {
                int c = warp_n * 32 + nt * 8 + lr;
                unsigned bh0 = *(unsigned*)&Wh_s[c * 40 + kc + lc2];
                unsigned bh1 = *(unsigned*)&Wh_s[c * 40 + kc + 8 + lc2];
                unsigned bl0 = *(unsigned*)&Wl_s[c * 40 + kc + lc2];
                unsigned bl1 = *(unsigned*)&Wl_s[c * 40 + kc + 8 + lc2];
#pragma unroll
                for (int mt = 0; mt < 2; mt++) {
                    MMA_BF16(acc[mt][nt], ah[mt], bh0, bh1);
                    MMA_BF16(acc[mt][nt], ah[mt], bl0, bl1);
                    MMA_BF16(acc[mt][nt], al[mt], bh0, bh1);
                }
            }
        }
        __syncthreads();
    }

    // Epilogue: head-layout scatter.
#pragma unroll
    for (int mt = 0; mt < 2; mt++) {
#pragma unroll
        for (int rr = 0; rr < 2; rr++) {
            int gm = row0 + warp_m * 32 + mt * 16 + lr + rr * 8;
            int b = gm >> 11, s = gm & 2047;
#pragma unroll
            for (int nt = 0; nt < 4; nt++) {
#pragma unroll
                for (int cc = 0; cc < 2; cc++) {
                    int gn = col0 + warp_n * 32 + nt * 8 + lc2 + cc;
                    int h = gn >> 6, d = gn & 63;
                    long long ci = (((long long)(b * HH + h)) * SS + s) * DH + d;
                    float val = acc[mt][nt][rr * 2 + cc] + gld(bias, gn, DM);
                    if (DSTSEL == 2) {
                        gst(g_v, ci, QKV_ELEMS, val);
                    } else {
                        __nv_bfloat16 hh, ll;
                        f2bf2(val, hh, ll);
                        gstb((DSTSEL == 0) ? g_qh : g_kh, ci, QKV_ELEMS, hh);
                        gstb((DSTSEL == 0) ? g_ql : g_kl, ci, QKV_ELEMS, ll);
                    }
                }
            }
        }
    }
}

// ===========================================================================
// Output projection via bf16x3 mma: out = gather(ctx bf16 hi/lo) @ W_o^T + b_o.
// A is pre-split (g_ctxh/g_ctxl from av); only W_o split in-kernel.
// ===========================================================================
__global__ void __launch_bounds__(256) out_proj_mma_kernel(
    const float* __restrict__ W, const float* __restrict__ bias,
    float* __restrict__ out)
{
    __shared__ __nv_bfloat16 Ah_s[128 * 40];
    __shared__ __nv_bfloat16 Al_s[128 * 40];
    __shared__ __nv_bfloat16 Wh_s[64 * 40];
    __shared__ __nv_bfloat16 Wl_s[64 * 40];

    const int tid = threadIdx.x;
    const int warp = tid >> 5, lane = tid & 31;
    const int warp_m = warp & 3, warp_n = warp >> 2;
    const int row0 = blockIdx.y * 128, col0 = blockIdx.x * 64;
    const int lr = lane >> 2, lc2 = (lane & 3) * 2;

    float acc[2][4][4];
#pragma unroll
    for (int a = 0; a < 2; a++)
#pragma unroll
        for (int b = 0; b < 4; b++)
#pragma unroll
            for (int c = 0; c < 4; c++) acc[a][b][c] = 0.f;

    for (int k0 = 0; k0 < DM; k0 += 32) {
        // A tile 128x32 from pre-split ctx (head-layout gather; 4B groups stay in-head)
#pragma unroll
        for (int it = 0; it < 4; it++) {
            int v = tid + it * 256;
            int m = v >> 3;
            int kq = (v & 7) * 4;
            int gm = row0 + m;
            int gk = k0 + kq;
            int b = gm >> 11, s = gm & 2047;
            int h = gk >> 6, d = gk & 63;
            long long ai = (((long long)(b * HH + h)) * SS + s) * DH + d;
            *(uint2*)&Ah_s[m * 40 + kq] = gldb4(g_ctxh, ai, QKV_ELEMS);
            *(uint2*)&Al_s[m * 40 + kq] = gldb4(g_ctxl, ai, QKV_ELEMS);
        }
        // W tile 64x32 fp32 -> hi/lo
#pragma unroll
        for (int it = 0; it < 2; it++) {
            int v = tid + it * 256;
            int n = v >> 3;
            int kq = (v & 7) * 4;
            float4 w = gld4(W, (long long)(col0 + n) * DM + k0 + kq, W_ELEMS);
            uint2 h, l;
            split4(w, h, l);
            *(uint2*)&Wh_s[n * 40 + kq] = h;
            *(uint2*)&Wl_s[n * 40 + kq] = l;
        }
        __syncthreads();

#pragma unroll
        for (int kc = 0; kc < 32; kc += 16) {
            unsigned ah[2][4], al[2][4];
#pragma unroll
            for (int mt = 0; mt < 2; mt++) {
                int r = warp_m * 32 + mt * 16 + lr;
                ah[mt][0] = *(unsigned*)&Ah_s[r * 40 + kc + lc2];
                ah[mt][1] = *(unsigned*)&Ah_s[(r + 8) * 40 + kc + lc2];
                ah[mt][2] = *(unsigned*)&Ah_s[r * 40 + kc + 8 + lc2];
                ah[mt][3] = *(unsigned*)&Ah_s[(r + 8) * 40 + kc + 8 + lc2];
                al[mt][0] = *(unsigned*)&Al_s[r * 40 + kc + lc2];
                al[mt][1] = *(unsigned*)&Al_s[(r + 8) * 40 + kc + lc2];
                al[mt][2] = *(unsigned*)&Al_s[r * 40 + kc + 8 + lc2];
                al[mt][3] = *(unsigned*)&Al_s[(r + 8) * 40 + kc + 8 + lc2];
            }
#pragma unroll
            for (int nt = 0; nt < 4; nt++) {
                int c = warp_n * 32 + nt * 8 + lr;
                unsigned bh0 = *(unsigned*)&Wh_s[c * 40 + kc + lc2];
                unsigned bh1 = *(unsigned*)&Wh_s[c * 40 + kc + 8 + lc2];
                unsigned bl0 = *(unsigned*)&Wl_s[c * 40 + kc + lc2];
                unsigned bl1 = *(unsigned*)&Wl_s[c * 40 + kc + 8 + lc2];
#pragma unroll
                for (int mt = 0; mt < 2; mt++) {
                    MMA_BF16(acc[mt][nt], ah[mt], bh0, bh1);
                    MMA_BF16(acc[mt][nt], ah[mt], bl0, bl1);
                    MMA_BF16(acc[mt][nt], al[mt], bh0, bh1);
                }
            }
        }
        __syncthreads();
    }

#pragma unroll
    for (int mt = 0; mt < 2; mt++) {
#pragma unroll
        for (int rr = 0; rr < 2; rr++) {
            int gm = row0 + warp_m * 32 + mt * 16 + lr + rr * 8;
#pragma unroll
            for (int nt = 0; nt < 4; nt++) {
#pragma unroll
                for (int cc = 0; cc < 2; cc++) {
                    int gn = col0 + warp_n * 32 + nt * 8 + lc2 + cc;
                    gst(out, (long long)gm * DM + gn, OUT_ELEMS,
                        acc[mt][nt][rr * 2 + cc] + gld(bias, gn, DM));
                }
            }
        }
    }
}

// ===========================================================================
// Scores via bf16x3 mma (round-10, unchanged).
// ===========================================================================
#define SCORES_SMEM 73728

__global__ void __launch_bounds__(256) scores_mma_kernel(float* __restrict__ attn)
{
    extern __shared__ __align__(16) char smraw[];
    __nv_bfloat16* Qh_s = (__nv_bfloat16*)smraw;
    __nv_bfloat16* Ql_s = (__nv_bfloat16*)(smraw + 18432);
    __nv_bfloat16* Kh_s = (__nv_bfloat16*)(smraw + 36864);
    __nv_bfloat16* Kl_s = (__nv_bfloat16*)(smraw + 55296);

    const int tid = threadIdx.x;
    const int warp = tid >> 5;
    const int lane = tid & 31;
    const int warp_m = warp & 3;
    const int warp_n = warp >> 2;
    const int bh = blockIdx.z;
    const int row0 = blockIdx.y * 128;
    const int col0 = blockIdx.x * 128;
    const long long hb = (long long)bh * SS * DH;

#pragma unroll
    for (int it = 0; it < 8; it++) {
        int v = tid + it * 256;
        int m = v >> 4;
        int kq = (v & 15) * 4;
        long long qi = hb + (long long)(row0 + m) * DH + kq;
        *(uint2*)&Qh_s[m * 72 + kq] = gldb4(g_qh, qi, QKV_ELEMS);
        *(uint2*)&Ql_s[m * 72 + kq] = gldb4(g_ql, qi, QKV_ELEMS);
        long long ki = hb + (long long)(col0 + m) * DH + kq;
        *(uint2*)&Kh_s[m * 72 + kq] = gldb4(g_kh, ki, QKV_ELEMS);
        *(uint2*)&Kl_s[m * 72 + kq] = gldb4(g_kl, ki, QKV_ELEMS);
    }
    __syncthreads();

    const int lr = lane >> 2;
    const int lc2 = (lane & 3) * 2;

    float acc[2][8][4];
#pragma unroll
    for (int a = 0; a < 2; a++)
#pragma unroll
        for (int b = 0; b < 8; b++)
#pragma unroll
            for (int c = 0; c < 4; c++) acc[a][b][c] = 0.f;

#pragma unroll
    for (int kc = 0; kc < 4; kc++) {
        int k0 = kc * 16;
        unsigned ah[2][4], al[2][4];
#pragma unroll
        for (int mt = 0; mt < 2; mt++) {
            int r = warp_m * 32 + mt * 16 + lr;
            ah[mt][0] = *(unsigned*)&Qh_s[r * 72 + k0 + lc2];
            ah[mt][1] = *(unsigned*)&Qh_s[(r + 8) * 72 + k0 + lc2];
            ah[mt][2] = *(unsigned*)&Qh_s[r * 72 + k0 + 8 + lc2];
            ah[mt][3] = *(unsigned*)&Qh_s[(r + 8) * 72 + k0 + 8 + lc2];
            al[mt][0] = *(unsigned*)&Ql_s[r * 72 + k0 + lc2];
            al[mt][1] = *(unsigned*)&Ql_s[(r + 8) * 72 + k0 + lc2];
            al[mt][2] = *(unsigned*)&Ql_s[r * 72 + k0 + 8 + lc2];
            al[mt][3] = *(unsigned*)&Ql_s[(r + 8) * 72 + k0 + 8 + lc2];
        }
#pragma unroll
        for (int nt = 0; nt < 8; nt++) {
            int c = warp_n * 64 + nt * 8 + lr;
            unsigned bh0 = *(unsigned*)&Kh_s[c * 72 + k0 + lc2];
            unsigned bh1 = *(unsigned*)&Kh_s[c * 72 + k0 + 8 + lc2];
            unsigned bl0 = *(unsigned*)&Kl_s[c * 72 + k0 + lc2];
            unsigned bl1 = *(unsigned*)&Kl_s[c * 72 + k0 + 8 + lc2];
#pragma unroll
            for (int mt = 0; mt < 2; mt++) {
                MMA_BF16(acc[mt][nt], ah[mt], bh0, bh1);
                MMA_BF16(acc[mt][nt], ah[mt], bl0, bl1);
                MMA_BF16(acc[mt][nt], al[mt], bh0, bh1);
            }
        }
    }

#pragma unroll
    for (int mt = 0; mt < 2; mt++) {
        int mrow = row0 + warp_m * 32 + mt * 16 + lr;
#pragma unroll
        for (int nt = 0; nt < 8; nt++) {
            int ncol = col0 + warp_n * 64 + nt * 8 + lc2;
            long long i0 = ((long long)bh * SS + mrow) * SS + ncol;
            long long i2 = ((long long)bh * SS + mrow + 8) * SS + ncol;
            gst(attn, i0,     ATTN_ELEMS, acc[mt][nt][0] * 0.125f);
            gst(attn, i0 + 1, ATTN_ELEMS, acc[mt][nt][1] * 0.125f);
            gst(attn, i2,     ATTN_ELEMS, acc[mt][nt][2] * 0.125f);
            gst(attn, i2 + 1, ATTN_ELEMS, acc[mt][nt][3] * 0.125f);
        }
    }
}

// ===========================================================================
// Row softmax over 2048 cols (unchanged).
// ===========================================================================
__global__ void __launch_bounds__(256) softmax_kernel(float* __restrict__ attn)
{
    __shared__ float red[8];
    const long long rbase = (long long)blockIdx.x * SS;
    const int tid = threadIdx.x;

    float4 v0 = gld4(attn, rbase + tid * 4, ATTN_ELEMS);
    float4 v1 = gld4(attn, rbase + 1024 + tid * 4, ATTN_ELEMS);

    float m = fmaxf(fmaxf(fmaxf(v0.x, v0.y), fmaxf(v0.z, v0.w)),
                    fmaxf(fmaxf(v1.x, v1.y), fmaxf(v1.z, v1.w)));
#pragma unroll
    for (int o = 16; o > 0; o >>= 1) m = fmaxf(m, __shfl_xor_sync(0xFFFFFFFFu, m, o));
    if ((tid & 31) == 0) red[tid >> 5] = m;
    __syncthreads();
    m = red[0];
#pragma unroll
    for (int w = 1; w < 8; w++) m = fmaxf(m, red[w]);
    __syncthreads();

    v0.x = __expf(v0.x - m); v0.y = __expf(v0.y - m);
    v0.z = __expf(v0.z - m); v0.w = __expf(v0.w - m);
    v1.x = __expf(v1.x - m); v1.y = __expf(v1.y - m);
    v1.z = __expf(v1.z - m); v1.w = __expf(v1.w - m);
    float s = v0.x + v0.y + v0.z + v0.w + v1.x + v1.y + v1.z + v1.w;
#pragma unroll
    for (int o = 16; o > 0; o >>= 1) s += __shfl_xor_sync(0xFFFFFFFFu, s, o);
    if ((tid & 31) == 0) red[tid >> 5] = s;
    __syncthreads();
    s = red[0];
#pragma unroll
    for (int w = 1; w < 8; w++) s += red[w];

    float inv = 1.f / s;
    v0.x *= inv; v0.y *= inv; v0.z *= inv; v0.w *= inv;
    v1.x *= inv; v1.y *= inv; v1.z *= inv; v1.w *= inv;

    long long i0 = rbase + tid * 4;
    long long i1 = rbase + 1024 + tid * 4;
    if (i0 + 3 < ATTN_ELEMS) *(float4*)(attn + i0) = v0;
    if (i1 + 3 < ATTN_ELEMS) *(float4*)(attn + i1) = v1;
}

// ===========================================================================
// AV via bf16x3 mma (round-10 + ctx emitted as bf16 hi/lo).
// ===========================================================================
#define AV_SMEM 55296

__global__ void __launch_bounds__(256) av_mma_kernel(const float* __restrict__ attn)
{
    extern __shared__ __align__(16) char smraw[];
    __nv_bfloat16* Ph_s  = (__nv_bfloat16*)smraw;
    __nv_bfloat16* Pl_s  = (__nv_bfloat16*)(smraw + 18432);
    __nv_bfloat16* Vth_s = (__nv_bfloat16*)(smraw + 36864);
    __nv_bfloat16* Vtl_s = (__nv_bfloat16*)(smraw + 46080);

    const int tid = threadIdx.x;
    const int warp = tid >> 5;
    const int lane = tid & 31;
    const int warp_m = warp & 3;
    const int warp_n = warp >> 2;
    const int bh = blockIdx.y;
    const int row0 = blockIdx.x * 128;
    const long long pbase = (long long)bh * SS * SS;
    const long long vbase = (long long)bh * SS * DH;

    const int lr = lane >> 2;
    const int lc2 = (lane & 3) * 2;

    float acc[2][4][4];
#pragma unroll
    for (int a = 0; a < 2; a++)
#pragma unroll
        for (int b = 0; b < 4; b++)
#pragma unroll
            for (int c = 0; c < 4; c++) acc[a][b][c] = 0.f;

    for (int kk = 0; kk < SS; kk += 64) {
#pragma unroll
        for (int it = 0; it < 8; it++) {
            int v = tid + it * 256;
            int m = v >> 4;
            int kq = (v & 15) * 4;
            float4 p = gld4(attn, pbase + (long long)(row0 + m) * SS + kk + kq, ATTN_ELEMS);
            uint2 h, l;
            split4(p, h, l);
            *(uint2*)&Ph_s[m * 72 + kq] = h;
            *(uint2*)&Pl_s[m * 72 + kq] = l;
        }
#pragma unroll
        for (int it = 0; it < 4; it++) {
            int v = tid + it * 256;
            int k = v >> 4;                  // 0..63
            int dq = (v & 15) * 4;           // 0..60
            float4 vv = gld4(g_v, vbase + (long long)(kk + k) * DH + dq, QKV_ELEMS);
            __nv_bfloat16 h, l;
            f2bf2(vv.x, h, l); Vth_s[(dq + 0) * 72 + k] = h; Vtl_s[(dq + 0) * 72 + k] = l;
            f2bf2(vv.y, h, l); Vth_s[(dq + 1) * 72 + k] = h; Vtl_s[(dq + 1) * 72 + k] = l;
            f2bf2(vv.z, h, l); Vth_s[(dq + 2) * 72 + k] = h; Vtl_s[(dq + 2) * 72 + k] = l;
            f2bf2(vv.w, h, l); Vth_s[(dq + 3) * 72 + k] = h; Vtl_s[(dq + 3) * 72 + k] = l;
        }
        __syncthreads();

#pragma unroll
        for (int kc = 0; kc < 4; kc++) {
            int k0 = kc * 16;
            unsigned ah[2][4], al[2][4];
#pragma unroll
            for (int mt = 0; mt < 2; mt++) {
                int r = warp_m * 32 + mt * 16 + lr;
                ah[mt][0] = *(unsigned*)&Ph_s[r * 72 + k0 + lc2];
                ah[mt][1] = *(unsigned*)&Ph_s[(r + 8) * 72 + k0 + lc2];
                ah[mt][2] = *(unsigned*)&Ph_s[r * 72 + k0 + 8 + lc2];
                ah[mt][3] = *(unsigned*)&Ph_s[(r + 8) * 72 + k0 + 8 + lc2];
                al[mt][0] = *(unsigned*)&Pl_s[r * 72 + k0 + lc2];
                al[mt][1] = *(unsigned*)&Pl_s[(r + 8) * 72 + k0 + lc2];
                al[mt][2] = *(unsigned*)&Pl_s[r * 72 + k0 + 8 + lc2];
                al[mt][3] = *(unsigned*)&Pl_s[(r + 8) * 72 + k0 + 8 + lc2];
            }
#pragma unroll
            for (int nt = 0; nt < 4; nt++) {
                int c = warp_n * 32 + nt * 8 + lr;
                unsigned bh0 = *(unsigned*)&Vth_s[c * 72 + k0 + lc2];
                unsigned bh1 = *(unsigned*)&Vth_s[c * 72 + k0 + 8 + lc2];
                unsigned bl0 = *(unsigned*)&Vtl_s[c * 72 + k0 + lc2];
                unsigned bl1 = *(unsigned*)&Vtl_s[c * 72 + k0 + 8 + lc2];
#pragma unroll
                for (int mt = 0; mt < 2; mt++) {
                    MMA_BF16(acc[mt][nt], ah[mt], bh0, bh1);
                    MMA_BF16(acc[mt][nt], ah[mt], bl0, bl1);
                    MMA_BF16(acc[mt][nt], al[mt], bh0, bh1);
                }
            }
        }
        __syncthreads();
    }

    // Epilogue: ctx as bf16 hi/lo (consumed pre-split by out_proj_mma).
#pragma unroll
    for (int mt = 0; mt < 2; mt++) {
#pragma unroll
        for (int rr = 0; rr < 2; rr++) {
            int mrow = row0 + warp_m * 32 + mt * 16 + lr + rr * 8;
#pragma unroll
            for (int nt = 0; nt < 4; nt++) {
#pragma unroll
                for (int cc = 0; cc < 2; cc++) {
                    int dcol = warp_n * 32 + nt * 8 + lc2 + cc;
                    long long ci = vbase + (long long)mrow * DH + dcol;
                    __nv_bfloat16 h, l;
                    f2bf2(acc[mt][nt][rr * 2 + cc], h, l);
                    gstb(g_ctxh, ci, QKV_ELEMS, h);
                    gstb(g_ctxl, ci, QKV_ELEMS, l);
                }
            }
        }
    }
}

// ---------------------------------------------------------------------------
static bool s_capturing_probe()
{
    cudaStreamCaptureStatus st = cudaStreamCaptureStatusNone;
    cudaError_t e = cudaStreamIsCapturing(0, &st);
    if (e != cudaSuccess) { cudaGetLastError(); return true; }
    return st != cudaStreamCaptureStatusNone;
}

static void diag(const char* name, bool capturing)
{
    if (capturing) return;  // launches only during graph capture
    cudaError_t e = cudaDeviceSynchronize();
    fprintf(stderr, "[klaunch] %s: %s\n", name, cudaGetErrorString(e));
    cudaGetLastError();
}

extern "C" void kernel_launch(void* const* d_in, const int* in_sizes, int n_in,
                              void* d_out, int out_size)
{
    const float* query = (const float*)d_in[0];
    const float* key   = (const float*)d_in[1];
    const float* value = (const float*)d_in[2];
    const float* W_q   = (const float*)d_in[3];
    const float* b_q   = (const float*)d_in[4];
    const float* W_k   = (const float*)d_in[5];
    const float* b_k   = (const float*)d_in[6];
    const float* W_v   = (const float*)d_in[7];
    const float* b_v   = (const float*)d_in[8];
    const float* W_o   = (const float*)d_in[9];
    const float* b_o   = (const float*)d_in[10];

    float* out  = (float*)d_out;
    float* attn = out + OUT_ELEMS;  // confirmed: out_size == OUT_ELEMS + ATTN_ELEMS

    const bool capturing = s_capturing_probe();

    cudaFuncSetAttribute(scores_mma_kernel,
                         cudaFuncAttributeMaxDynamicSharedMemorySize, SCORES_SMEM);
    cudaFuncSetAttribute(av_mma_kernel,
                         cudaFuncAttributeMaxDynamicSharedMemorySize, AV_SMEM);

    dim3 gProj(DM / 64, MM / 128);              // (12, 32)
    dim3 gScores(SS / 128, SS / 128, BB * HH);  // (16, 16, 24)
    dim3 gAV(SS / 128, BB * HH);                // (16, 24)

    proj_mma_kernel<0><<<gProj, 256>>>(query, W_q, b_q);
    diag("proj_q", capturing);
    proj_mma_kernel<1><<<gProj, 256>>>(key, W_k, b_k);
    diag("proj_k", capturing);
    proj_mma_kernel<2><<<gProj, 256>>>(value, W_v, b_v);
    diag("proj_v", capturing);

    scores_mma_kernel<<<gScores, 256, SCORES_SMEM>>>(attn);
    diag("scores_mma", capturing);

    softmax_kernel<<<BB * HH * SS, 256>>>(attn);
    diag("softmax", capturing);

    av_mma_kernel<<<gAV, 256, AV_SMEM>>>(attn);
    diag("av_mma", capturing);

    out_proj_mma_kernel<<<gProj, 256>>>(W_o, b_o, out);
    diag("out_proj", capturing);
}